// round 3
// baseline (speedup 1.0000x reference)
#include <cuda_runtime.h>
#include <cuda_bf16.h>

// CTC forward, one block (128 threads = 4 warps) per batch element.
// Thread i owns pair (E_i = state 2i, O_i = state 2i+1) in registers.
// Only O_{i-1} crosses threads:
//   - intra-warp: __shfl_up_sync (no smem, no barrier)
//   - cross-warp: lock-free smem ring, one 64-bit (stamp|value) word per step,
//     unique slot per t (no wraparound) -> warps form a self-timed pipeline,
//     ZERO block barriers in the main loop.
// Alphas in log2 domain (emissions pre-scaled by log2 e).

#define NEGF  (-1e30f)
#define LOG2E 1.4426950408889634f
#define LN2   0.6931471805599453f
#define MAXB  1024
#define MAXT  1024   // max time steps supported by ring (T=1024 here)

__device__ float        g_per_ex[MAXB];
__device__ unsigned int g_count = 0;

__device__ __forceinline__ float lse2(float a, float b) {
    float m = fmaxf(a, b);
    float d = fminf(a, b) - m;          // <= 0
    return m + __log2f(1.0f + exp2f(d));
}

__global__ __launch_bounds__(128, 1)
void ctc_forward_kernel(const float* __restrict__ pred,           // (B, T, C)
                        const int*   __restrict__ targets,        // (B, L)
                        const int*   __restrict__ pred_lengths,   // (B,)
                        const int*   __restrict__ target_lengths, // (B,)
                        float*       __restrict__ out,
                        int T, int C, int L, int B)
{
    __shared__ unsigned long long ring[3][MAXT];  // [producer warp][t] = (stamp<<32)|O bits
    __shared__ float sOf[129];
    __shared__ float sEf[130];
    __shared__ unsigned int s_last;
    __shared__ float sred[4];

    const int b    = blockIdx.x;
    const int i    = threadIdx.x;        // pair index 0..127
    const int w    = i >> 5;
    const int lane = i & 31;

    // zero ring stamps (slots written once, stamp t+1 != 0)
    for (int k = i; k < 3 * MAXT; k += 128)
        (&ring[0][0])[k] = 0ull;

    const int  li   = (i < L) ? i : (L - 1);
    const int  lbl  = targets[(size_t)b * L + li];
    const int  prev = (li >= 1) ? targets[(size_t)b * L + li - 1] : -1;
    const bool skip = (lbl != 0) && (lbl != prev);

    const float* rowp = pred + (size_t)b * T * C;

    int pl = pred_lengths[b];
    int Teff = pl < T ? pl : T; if (Teff < 1) Teff = 1;
    const int steps = Teff - 1;          // updates at t = 1..steps (<= MAXT-1)

    // ---- init (t = 0) ----
    float eb0 = __ldg(rowp) * LOG2E;
    float el0 = __ldg(rowp + lbl) * LOG2E;
    float E  = (i == 0) ? eb0 : NEGF;    // state 2i
    float O  = (i == 0) ? el0 : NEGF;    // state 2i+1
    float E2 = NEGF;                     // state 2L (thread 127 only)

    // emission prefetch ring, depth 8
    float eb[8], el[8];
#pragma unroll
    for (int j = 0; j < 8; j++) {
        int tt = 1 + j; if (tt > steps) tt = steps; if (tt < 0) tt = 0;
        const float* p = rowp + (size_t)tt * C;
        eb[j] = __ldg(p) * LOG2E;
        el[j] = __ldg(p + lbl) * LOG2E;
    }

    __syncthreads();   // ring zeroed before producers write

    // producers publish O(0) in slot 0 with stamp 1
    if (w < 3 && lane == 31)
        *(volatile unsigned long long*)&ring[w][0] =
            (1ull << 32) | (unsigned long long)__float_as_uint(O);

    int t = 1;
    // ---- main loop: no barriers ----
    for (; t + 7 <= steps; t += 8) {
#pragma unroll
        for (int j = 0; j < 8; j++) {
            const int tc = t + j;
            // fetch O_{i-1}(tc-1)
            float Om1;
            if (w == 0) {
                float sh = __shfl_up_sync(0xffffffffu, O, 1);
                Om1 = (lane == 0) ? NEGF : sh;
            } else {
                volatile unsigned long long* sp = &ring[w - 1][tc - 1];
                unsigned long long v = *sp;                 // issued before shfl
                float sh = __shfl_up_sync(0xffffffffu, O, 1);
                while ((unsigned)(v >> 32) != (unsigned)tc) v = *sp;   // warp-uniform
                Om1 = (lane == 0) ? __uint_as_float((unsigned)(v & 0xffffffffu)) : sh;
            }
            float Om1s = skip ? Om1 : NEGF;

            if (i == 127) E2 = lse2(E2, O) + eb[j];   // uses old O (own reg)

            // O update: 3-way lse, fmax(O,E) precomputable off-chain
            float m1 = fmaxf(O, E);
            float mO = fmaxf(m1, Om1s);
            float s3 = exp2f(O - mO) + exp2f(E - mO) + exp2f(Om1s - mO);
            float nO = mO + __log2f(s3) + el[j];
            // E update: 2-way lse
            float nE = lse2(E, Om1) + eb[j];

            if (w < 3 && lane == 31)
                *(volatile unsigned long long*)&ring[w][tc] =
                    (((unsigned long long)(unsigned)(tc + 1)) << 32)
                    | (unsigned long long)__float_as_uint(nO);

            O = nO; E = nE;

            // prefetch step tc+8
            int tt = tc + 8; if (tt > steps) tt = steps;
            const float* p = rowp + (size_t)tt * C;
            eb[j] = __ldg(p) * LOG2E;
            el[j] = __ldg(p + lbl) * LOG2E;
        }
    }
    // ---- remainder (< 8 steps), direct loads ----
    for (; t <= steps; t++) {
        const float* p = rowp + (size_t)t * C;
        float ebx = __ldg(p) * LOG2E;
        float elx = __ldg(p + lbl) * LOG2E;

        float Om1;
        if (w == 0) {
            float sh = __shfl_up_sync(0xffffffffu, O, 1);
            Om1 = (lane == 0) ? NEGF : sh;
        } else {
            volatile unsigned long long* sp = &ring[w - 1][t - 1];
            unsigned long long v = *sp;
            float sh = __shfl_up_sync(0xffffffffu, O, 1);
            while ((unsigned)(v >> 32) != (unsigned)t) v = *sp;
            Om1 = (lane == 0) ? __uint_as_float((unsigned)(v & 0xffffffffu)) : sh;
        }
        float Om1s = skip ? Om1 : NEGF;

        if (i == 127) E2 = lse2(E2, O) + ebx;

        float m1 = fmaxf(O, E);
        float mO = fmaxf(m1, Om1s);
        float s3 = exp2f(O - mO) + exp2f(E - mO) + exp2f(Om1s - mO);
        float nO = mO + __log2f(s3) + elx;
        float nE = lse2(E, Om1) + ebx;

        if (w < 3 && lane == 31)
            *(volatile unsigned long long*)&ring[w][t] =
                (((unsigned long long)(unsigned)(t + 1)) << 32)
                | (unsigned long long)__float_as_uint(nO);

        O = nO; E = nE;
    }

    // ---- gather + per-example loss ----
    sOf[i] = O;                 // O_i
    sEf[i] = E;                 // E_i
    if (i == 127) sEf[128] = E2;
    __syncthreads();

    if (i == 0) {
        int tl = target_lengths[b];
        int tlc = tl; if (tlc < 1) tlc = 1; if (tlc > L) tlc = L;
        float l1 = sOf[tlc - 1];        // state 2*tl - 1
        float l2 = sEf[tlc];            // state 2*tl
        float per = -(lse2(l1, l2) * LN2);
        if (per > 1e29f) per = 0.0f;
        int denom = tl < 1 ? 1 : tl;
        g_per_ex[b] = per / (float)denom;
        __threadfence();
        unsigned prevc = atomicAdd(&g_count, 1u);
        s_last = (prevc == (unsigned)(B - 1)) ? 1u : 0u;
    }
    __syncthreads();

    // ---- last block computes the batch mean (deterministic fixed order) ----
    if (s_last) {
        float v = 0.f;
        for (int idx = i; idx < B; idx += 128)
            v += *((volatile float*)&g_per_ex[idx]);
#pragma unroll
        for (int o = 16; o > 0; o >>= 1)
            v += __shfl_down_sync(0xffffffffu, v, o);
        if (lane == 0) sred[w] = v;
        __syncthreads();
        if (i == 0) {
            float tot = sred[0] + sred[1] + sred[2] + sred[3];
            out[0] = tot / (float)B;
            g_count = 0;    // reset for next graph replay
        }
    }
}

extern "C" void kernel_launch(void* const* d_in, const int* in_sizes, int n_in,
                              void* d_out, int out_size)
{
    const float* pred           = (const float*)d_in[0];
    const int*   targets        = (const int*)d_in[1];
    const int*   pred_lengths   = (const int*)d_in[2];
    const int*   target_lengths = (const int*)d_in[3];

    const int B = in_sizes[2];
    const int L = in_sizes[1] / B;
    const int C = 128;
    const int T = (in_sizes[0] / B) / C;

    ctc_forward_kernel<<<B, 128>>>(pred, targets, pred_lengths, target_lengths,
                                   (float*)d_out, T, C, L, B);
}

// round 4
// speedup vs baseline: 1.8164x; 1.8164x over previous
#include <cuda_runtime.h>
#include <cuda_bf16.h>

// CTC forward, one block (128 threads = 4 warps) per batch element.
// Thread i owns pair (E_i = state 2i, O_i = state 2i+1) in registers.
// Only O_{i-1} crosses threads: double-buffered smem row + one __syncthreads
// per step. Critical chain kept minimal: nothing executes between the STS of
// nO and the barrier arrival. Alphas in log2 domain.

#define NEGF  (-1e30f)
#define LOG2E 1.4426950408889634f
#define LN2   0.6931471805599453f
#define MAXB  1024

__device__ float        g_per_ex[MAXB];
__device__ unsigned int g_count = 0;

__device__ __forceinline__ float lse2(float a, float b) {
    float m = fmaxf(a, b);
    float d = fminf(a, b) - m;          // <= 0
    return m + __log2f(1.0f + exp2f(d));
}

__global__ __launch_bounds__(128, 1)
void ctc_forward_kernel(const float* __restrict__ pred,           // (B, T, C)
                        const int*   __restrict__ targets,        // (B, L)
                        const int*   __restrict__ pred_lengths,   // (B,)
                        const int*   __restrict__ target_lengths, // (B,)
                        float*       __restrict__ out,
                        int T, int C, int L, int B)
{
    __shared__ float sO[2][130];   // O_i stored at [i+1]; [0] = NEG sentinel
    __shared__ float sOf[129];
    __shared__ float sEf[130];
    __shared__ unsigned int s_last;
    __shared__ float sred[4];

    const int b    = blockIdx.x;
    const int i    = threadIdx.x;        // pair index 0..127
    const int w    = i >> 5;
    const int lane = i & 31;

    const int  li   = (i < L) ? i : (L - 1);
    const int  lbl  = targets[(size_t)b * L + li];
    const int  prev = (li >= 1) ? targets[(size_t)b * L + li - 1] : -1;
    const bool skip = (lbl != 0) && (lbl != prev);

    const float* rowp = pred + (size_t)b * T * C;

    int pl = pred_lengths[b];
    int Teff = pl < T ? pl : T; if (Teff < 1) Teff = 1;
    const int steps = Teff - 1;          // updates at t = 1..steps

    // ---- init (t = 0) ----
    float eb0 = __ldg(rowp) * LOG2E;
    float el0 = __ldg(rowp + lbl) * LOG2E;
    float E  = (i == 0) ? eb0 : NEGF;    // state 2i
    float O  = (i == 0) ? el0 : NEGF;    // state 2i+1
    float E2 = NEGF;                     // state 2L (thread 127 only)

    if (i == 0) { sO[0][0] = NEGF; sO[1][0] = NEGF; }
    sO[0][i + 1] = O;

    // emission prefetch ring, depth 8
    float eb[8], el[8];
#pragma unroll
    for (int j = 0; j < 8; j++) {
        int tt = 1 + j; if (tt > steps) tt = steps; if (tt < 0) tt = 0;
        const float* p = rowp + (size_t)tt * C;
        eb[j] = __ldg(p) * LOG2E;
        el[j] = __ldg(p + lbl) * LOG2E;
    }

    __syncthreads();

    int t = 1;
    // ---- main loop: unroll 8, compile-time ping-pong (parity period 2) ----
    for (; t + 7 <= steps; t += 8) {
#pragma unroll
        for (int j = 0; j < 8; j++) {
            const int rb = j & 1;
            // critical load first
            float Om1 = sO[rb][i];                 // O_{i-1}(t-1), sentinel at [0]

            // off-chain work overlapping the LDS window:
            if (i == 127) E2 = lse2(E2, O) + eb[j];   // uses old O (own reg)
            int tt = t + j + 8; if (tt > steps) tt = steps;
            const float* p = rowp + (size_t)tt * C;
            float neb = __ldg(p) * LOG2E;
            float nel = __ldg(p + lbl) * LOG2E;
            float m1 = fmaxf(O, E);                 // own regs, ready early

            // O update: 3-way lse
            float Om1s = skip ? Om1 : NEGF;
            float mO = fmaxf(m1, Om1s);
            float s3 = exp2f(O - mO) + exp2f(E - mO) + exp2f(Om1s - mO);
            float nO = mO + __log2f(s3) + el[j];
            // E update: 2-way lse (parallel chain, not needed for STS)
            float nE = lse2(E, Om1) + eb[j];

            sO[rb ^ 1][i + 1] = nO;
            O = nO; E = nE;
            eb[j] = neb; el[j] = nel;
            __syncthreads();
        }
    }
    // ---- remainder (< 8 steps) ----
    {
        int rb = 0;
        for (int j = 0; t <= steps; t++, j++) {
            float Om1 = sO[rb][i];
            if (i == 127) E2 = lse2(E2, O) + eb[j];
            float m1 = fmaxf(O, E);
            float Om1s = skip ? Om1 : NEGF;
            float mO = fmaxf(m1, Om1s);
            float s3 = exp2f(O - mO) + exp2f(E - mO) + exp2f(Om1s - mO);
            float nO = mO + __log2f(s3) + el[j];
            float nE = lse2(E, Om1) + eb[j];
            sO[rb ^ 1][i + 1] = nO;
            O = nO; E = nE;
            rb ^= 1;
            __syncthreads();
        }
    }

    // ---- gather + per-example loss ----
    sOf[i] = O;
    sEf[i] = E;
    if (i == 127) sEf[128] = E2;
    __syncthreads();

    if (i == 0) {
        int tl = target_lengths[b];
        int tlc = tl; if (tlc < 1) tlc = 1; if (tlc > L) tlc = L;
        float l1 = sOf[tlc - 1];        // state 2*tl - 1
        float l2 = sEf[tlc];            // state 2*tl
        float per = -(lse2(l1, l2) * LN2);
        if (per > 1e29f) per = 0.0f;
        int denom = tl < 1 ? 1 : tl;
        g_per_ex[b] = per / (float)denom;
        __threadfence();
        unsigned prevc = atomicAdd(&g_count, 1u);
        s_last = (prevc == (unsigned)(B - 1)) ? 1u : 0u;
    }
    __syncthreads();

    // ---- last block computes the batch mean (deterministic fixed order) ----
    if (s_last) {
        float v = 0.f;
        for (int idx = i; idx < B; idx += 128)
            v += *((volatile float*)&g_per_ex[idx]);
#pragma unroll
        for (int o = 16; o > 0; o >>= 1)
            v += __shfl_down_sync(0xffffffffu, v, o);
        if (lane == 0) sred[w] = v;
        __syncthreads();
        if (i == 0) {
            float tot = sred[0] + sred[1] + sred[2] + sred[3];
            out[0] = tot / (float)B;
            g_count = 0;    // reset for next graph replay
        }
    }
}

extern "C" void kernel_launch(void* const* d_in, const int* in_sizes, int n_in,
                              void* d_out, int out_size)
{
    const float* pred           = (const float*)d_in[0];
    const int*   targets        = (const int*)d_in[1];
    const int*   pred_lengths   = (const int*)d_in[2];
    const int*   target_lengths = (const int*)d_in[3];

    const int B = in_sizes[2];
    const int L = in_sizes[1] / B;
    const int C = 128;
    const int T = (in_sizes[0] / B) / C;

    ctc_forward_kernel<<<B, 128>>>(pred, targets, pred_lengths, target_lengths,
                                   (float*)d_out, T, C, L, B);
}